// round 1
// baseline (speedup 1.0000x reference)
#include <cuda_runtime.h>
#include <cuda_bf16.h>
#include <math.h>

// ---------------- problem constants ----------------
#define BGR   128
#define NAT   32
#define NODES 4096          // BGR*NAT
#define NEDGE 131072        // BGR*NAT*NAT
#define HID   256
#define TDIM  128
#define TYPED 100
#define NFQ   10
#define EDIM  66            // NFQ*2*3 + 6
#define NLAY  4

// ---------------- scratch (device globals; no allocation allowed) ----------------
__device__ float g_feat[NODES * 384];
__device__ float g_nf  [NODES * HID];
__device__ float g_h   [NODES * HID];
__device__ float g_Pi  [NODES * HID];
__device__ float g_Pj  [NODES * HID];
__device__ float g_msg [NODES * HID];
__device__ float g_act [NODES * HID];
__device__ float g_gf  [BGR * HID];
__device__ float g_ef  [(size_t)NEDGE * EDIM];
__device__ float g_EfW [(size_t)NEDGE * HID];

__device__ __forceinline__ float silu_f(float x) {
    return x / (1.0f + __expf(-x));
}

// ---------------- generic fp32 GEMM ----------------
// C[M,N] (ldc) = epilogue( A[:,0:K0]@W[0:K0,:] + A1[:,0:K1]@W[K0:,:] + bias )
// A0 row stride == K0, A1 row stride == K1, W row-major with stride ldw.
// mode 0: C = acc+bias ; mode 1: C = silu(acc+bias) ; mode 2: C += silu(acc+bias)
#define GBM 64
#define GBN 64
#define GBK 16
__global__ void __launch_bounds__(256) gemm_kernel(
    const float* __restrict__ A0, int K0,
    const float* __restrict__ A1, int K1,
    const float* __restrict__ W, int ldw,
    const float* __restrict__ bias,
    float* __restrict__ C, int ldc,
    int M, int N, int mode)
{
    __shared__ float As[GBK][GBM + 1];
    __shared__ float Wsm[GBK][GBN];
    const int tid = threadIdx.x;
    const int tx = tid & 15;          // 16 col groups (4 cols each)
    const int ty = tid >> 4;          // 16 row groups (4 rows each)
    const int row0 = blockIdx.x * GBM;
    const int col0 = blockIdx.y * GBN;
    const int K = K0 + K1;

    float acc[4][4] = {};

    for (int kt = 0; kt < K; kt += GBK) {
        // load A tile (64 x 16): thread -> row tid/4, k = (tid%4)*4 + i
        {
            const int m  = tid >> 2;
            const int kb = (tid & 3) * 4;
            const int gr = row0 + m;
            #pragma unroll
            for (int i = 0; i < 4; i++) {
                const int k  = kb + i;
                const int gk = kt + k;
                float v = 0.0f;
                if (gk < K) {
                    if (gk < K0) v = A0[(size_t)gr * K0 + gk];
                    else         v = A1[(size_t)gr * K1 + (gk - K0)];
                }
                As[k][m] = v;
            }
        }
        // load W tile (16 x 64)
        #pragma unroll
        for (int i = 0; i < 4; i++) {
            const int idx = tid + 256 * i;
            const int k = idx >> 6;
            const int n = idx & 63;
            const int gk = kt + k;
            const int gn = col0 + n;
            Wsm[k][n] = (gk < K && gn < N) ? W[(size_t)gk * ldw + gn] : 0.0f;
        }
        __syncthreads();
        #pragma unroll
        for (int k = 0; k < GBK; k++) {
            float a[4], w[4];
            #pragma unroll
            for (int i = 0; i < 4; i++) a[i] = As[k][ty * 4 + i];
            #pragma unroll
            for (int i = 0; i < 4; i++) w[i] = Wsm[k][tx * 4 + i];
            #pragma unroll
            for (int i = 0; i < 4; i++)
                #pragma unroll
                for (int j = 0; j < 4; j++)
                    acc[i][j] = fmaf(a[i], w[j], acc[i][j]);
        }
        __syncthreads();
    }

    #pragma unroll
    for (int i = 0; i < 4; i++) {
        const int r = row0 + ty * 4 + i;
        if (r >= M) continue;
        #pragma unroll
        for (int j = 0; j < 4; j++) {
            const int c = col0 + tx * 4 + j;
            if (c >= N) continue;
            float v = acc[i][j];
            if (bias) v += bias[c];
            if (mode == 1)      v = silu_f(v);
            else if (mode == 2) v = C[(size_t)r * ldc + c] + silu_f(v);
            C[(size_t)r * ldc + c] = v;
        }
    }
}

// ---------------- time embedding -> feat[:,256:384] ----------------
__global__ void timefeat_kernel(const float* __restrict__ t, float* __restrict__ feat)
{
    const int idx = blockIdx.x * blockDim.x + threadIdx.x;  // NODES*128
    if (idx >= NODES * 128) return;
    const int node = idx >> 7;
    const int c = idx & 127;
    const int b = node >> 5;
    const float tv = t[b];
    const float kfac = -logf(10000.0f) / 63.0f;
    float val;
    if (c < 64) val = sinf(tv * __expf((float)c * kfac));
    else        val = cosf(tv * __expf((float)(c - 64) * kfac));
    feat[(size_t)node * 384 + 256 + c] = val;
}

// ---------------- edge features ef[E,66] (computed once) ----------------
__global__ void edgefeat_kernel(const float* __restrict__ frac,
                                const float* __restrict__ lpolar,
                                float* __restrict__ ef)
{
    const long long total = (long long)NEDGE * EDIM;
    long long idx = (long long)blockIdx.x * blockDim.x + threadIdx.x;
    if (idx >= total) return;
    const int e = (int)(idx / EDIM);
    const int c = (int)(idx - (long long)e * EDIM);
    const int b = e >> 10;
    const int j = e & 31;
    const int ei_node = e >> 5;            // b*32 + i
    const int ej_node = (b << 5) | j;      // b*32 + j

    float val;
    if (c < 60) {
        const int cc  = (c < 30) ? c : (c - 30);
        const int dim = cc / NFQ;
        const int f   = cc - dim * NFQ;
        float d = frac[ej_node * 3 + dim] - frac[ei_node * 3 + dim];
        d = d - floorf(d);                 // jnp.mod(x, 1.0)
        const float arg = d * (6.283185307179586f * (float)f);
        val = (c < 30) ? sinf(arg) : cosf(arg);
    } else {
        val = lpolar[b * 6 + (c - 60)];
    }
    ef[(size_t)e * EDIM + c] = val;
}

// ---------------- layernorm (row of 256) ----------------
__global__ void layernorm_kernel(const float* __restrict__ x,
                                 const float* __restrict__ g,
                                 const float* __restrict__ b,
                                 float* __restrict__ y)
{
    const int row = blockIdx.x;
    const int tid = threadIdx.x;  // 256
    const float v = x[(size_t)row * HID + tid];
    __shared__ float sred[8];

    float s = v;
    #pragma unroll
    for (int o = 16; o; o >>= 1) s += __shfl_xor_sync(0xffffffffu, s, o);
    if ((tid & 31) == 0) sred[tid >> 5] = s;
    __syncthreads();
    float tot = 0.0f;
    #pragma unroll
    for (int i = 0; i < 8; i++) tot += sred[i];
    const float mean = tot * (1.0f / 256.0f);
    const float d = v - mean;
    __syncthreads();

    float q = d * d;
    #pragma unroll
    for (int o = 16; o; o >>= 1) q += __shfl_xor_sync(0xffffffffu, q, o);
    if ((tid & 31) == 0) sred[tid >> 5] = q;
    __syncthreads();
    tot = 0.0f;
    #pragma unroll
    for (int i = 0; i < 8; i++) tot += sred[i];
    const float var = tot * (1.0f / 256.0f);

    y[(size_t)row * HID + tid] = d * rsqrtf(var + 1e-5f) * g[tid] + b[tid];
}

// ---------------- fused edge message kernel ----------------
// One block per target node: X[j] = silu(Pi[node] + Pj[src_j] + EfW[e]),
// Y = silu(X @ W2 + b2), msg[node] = sum_j Y[j] / 32.
#define EK_PAD 36
__global__ void __launch_bounds__(256, 1) edge_msg_kernel(
    const float* __restrict__ Pi, const float* __restrict__ Pj,
    const float* __restrict__ EfW, const float* __restrict__ W2,
    const float* __restrict__ b2, float* __restrict__ msg)
{
    extern __shared__ float sm[];
    float* XsT = sm;                      // [256][EK_PAD]  silu(X) transposed: XsT[k][j]
    float* W2s = sm + 256 * EK_PAD;       // [64][256]
    float* red = W2s + 64 * 256;          // [8][256]

    const int node = blockIdx.x;
    const int b = node >> 5;
    const int tid = threadIdx.x;          // 256, thread == column in phase 1

    // ---- phase 1: presum + silu ----
    const float base = Pi[(size_t)node * HID + tid];   // includes m1 bias
    #pragma unroll 4
    for (int j = 0; j < 32; j++) {
        const float v = base
            + Pj[(size_t)((b << 5) + j) * HID + tid]
            + EfW[((size_t)node * 32 + j) * HID + tid];
        XsT[tid * EK_PAD + j] = silu_f(v);
    }
    __syncthreads();

    // ---- phase 2: [32,256] @ W2[256,256] ----
    const int tx = tid & 31;   // cols tx*8 .. tx*8+7
    const int ty = tid >> 5;   // rows ty*4 .. ty*4+3
    float acc[4][8] = {};

    for (int kt = 0; kt < 256; kt += 64) {
        const float4* src = (const float4*)(W2 + (size_t)kt * 256);
        float4* dst = (float4*)W2s;
        #pragma unroll
        for (int i = 0; i < 16; i++)
            dst[tid + 256 * i] = src[tid + 256 * i];
        __syncthreads();

        #pragma unroll
        for (int k = 0; k < 64; k++) {
            const float4 a4 = *(const float4*)&XsT[(kt + k) * EK_PAD + ty * 4];
            const float* wrow = &W2s[k * 256 + tx * 8];
            float w[8];
            *(float4*)&w[0] = *(const float4*)&wrow[0];
            *(float4*)&w[4] = *(const float4*)&wrow[4];
            const float a[4] = {a4.x, a4.y, a4.z, a4.w};
            #pragma unroll
            for (int r = 0; r < 4; r++)
                #pragma unroll
                for (int x = 0; x < 8; x++)
                    acc[r][x] = fmaf(a[r], w[x], acc[r][x]);
        }
        __syncthreads();
    }

    // ---- epilogue: bias, silu, partial row-sum ----
    #pragma unroll
    for (int x = 0; x < 8; x++) {
        const float bb = b2[tx * 8 + x];
        float t0 = 0.0f;
        #pragma unroll
        for (int r = 0; r < 4; r++) t0 += silu_f(acc[r][x] + bb);
        red[ty * 256 + tx * 8 + x] = t0;
    }
    __syncthreads();

    float m = 0.0f;
    #pragma unroll
    for (int w = 0; w < 8; w++) m += red[w * 256 + tid];
    msg[(size_t)node * HID + tid] = m * (1.0f / 32.0f);
}

// ---------------- graph mean ----------------
__global__ void graphmean_kernel(const float* __restrict__ h, float* __restrict__ gf)
{
    const int b = blockIdx.x;     // 128
    const int c = threadIdx.x;    // 256
    float s = 0.0f;
    #pragma unroll
    for (int i = 0; i < 32; i++) s += h[(size_t)((b << 5) + i) * HID + c];
    gf[(size_t)b * HID + c] = s * (1.0f / 32.0f);
}

// ---------------- launch ----------------
static void run_gemm(cudaStream_t s,
                     const float* A0, int K0, const float* A1, int K1,
                     const float* W, int ldw, const float* bias,
                     float* C, int ldc, int M, int N, int mode)
{
    dim3 grid((M + GBM - 1) / GBM, (N + GBN - 1) / GBN);
    gemm_kernel<<<grid, 256, 0, s>>>(A0, K0, A1, K1, W, ldw, bias, C, ldc, M, N, mode);
}

extern "C" void kernel_launch(void* const* d_in, const int* in_sizes, int n_in,
                              void* d_out, int out_size)
{
    const float* t          = (const float*)d_in[0];
    const float* atom_types = (const float*)d_in[1];
    const float* frac       = (const float*)d_in[2];
    const float* l_polar    = (const float*)d_in[3];
    // d_in[4] = node2graph (implied by layout; recomputed arithmetically)
    const float* Ws      = (const float*)d_in[5];
    const float* bs      = (const float*)d_in[6];
    const float* Wn      = (const float*)d_in[7];
    const float* bn      = (const float*)d_in[8];
    const float* ln_g    = (const float*)d_in[9];
    const float* ln_b    = (const float*)d_in[10];
    const float* m1_W    = (const float*)d_in[11];
    const float* m1_b    = (const float*)d_in[12];
    const float* m2_W    = (const float*)d_in[13];
    const float* m2_b    = (const float*)d_in[14];
    const float* a1_W    = (const float*)d_in[15];
    const float* a1_b    = (const float*)d_in[16];
    const float* a2_W    = (const float*)d_in[17];
    const float* a2_b    = (const float*)d_in[18];
    const float* fln_g   = (const float*)d_in[19];
    const float* fln_b   = (const float*)d_in[20];
    const float* type_W  = (const float*)d_in[21];
    const float* type_b  = (const float*)d_in[22];
    const float* polar_W = (const float*)d_in[23];
    const float* frac_W  = (const float*)d_in[24];
    float* out = (float*)d_out;

    float *feat, *nf, *h, *Pi, *Pj, *msg, *act, *gf, *ef, *EfW;
    cudaGetSymbolAddress((void**)&feat, g_feat);
    cudaGetSymbolAddress((void**)&nf,   g_nf);
    cudaGetSymbolAddress((void**)&h,    g_h);
    cudaGetSymbolAddress((void**)&Pi,   g_Pi);
    cudaGetSymbolAddress((void**)&Pj,   g_Pj);
    cudaGetSymbolAddress((void**)&msg,  g_msg);
    cudaGetSymbolAddress((void**)&act,  g_act);
    cudaGetSymbolAddress((void**)&gf,   g_gf);
    cudaGetSymbolAddress((void**)&ef,   g_ef);
    cudaGetSymbolAddress((void**)&EfW,  g_EfW);

    const int EDGE_SMEM = (256 * EK_PAD + 64 * 256 + 8 * 256) * (int)sizeof(float); // ~110 KB
    cudaFuncSetAttribute(edge_msg_kernel, cudaFuncAttributeMaxDynamicSharedMemorySize, EDGE_SMEM);

    cudaStream_t s = 0;  // harness captures the default-stream work via its own stream

    // node features
    timefeat_kernel<<<(NODES * 128 + 255) / 256, 256, 0, s>>>(t, feat);
    run_gemm(s, atom_types, TYPED, nullptr, 0, Ws, HID, bs, feat, 384, NODES, HID, 0);
    run_gemm(s, feat, 384, nullptr, 0, Wn, HID, bn, nf, HID, NODES, HID, 0);

    // edge features (layer independent)
    {
        long long total = (long long)NEDGE * EDIM;
        edgefeat_kernel<<<(unsigned)((total + 255) / 256), 256, 0, s>>>(frac, l_polar, ef);
    }

    for (int l = 0; l < NLAY; l++) {
        const float* W1 = m1_W + (size_t)l * 578 * HID;
        layernorm_kernel<<<NODES, 256, 0, s>>>(nf, ln_g + l * HID, ln_b + l * HID, h);
        // Pi = h @ W1[0:256] + m1_b  (bias folded here)
        run_gemm(s, h, HID, nullptr, 0, W1, HID, m1_b + l * HID, Pi, HID, NODES, HID, 0);
        // Pj = h @ W1[256:512]
        run_gemm(s, h, HID, nullptr, 0, W1 + 256 * HID, HID, nullptr, Pj, HID, NODES, HID, 0);
        // EfW = ef @ W1[512:578]
        run_gemm(s, ef, EDIM, nullptr, 0, W1 + 512 * HID, HID, nullptr, EfW, HID, NEDGE, HID, 0);
        // fused: silu presum -> @m2 -> silu -> scatter-mean
        edge_msg_kernel<<<NODES, 256, EDGE_SMEM, s>>>(
            Pi, Pj, EfW, m2_W + (size_t)l * HID * HID, m2_b + l * HID, msg);
        // a = silu(concat(nf,msg) @ a1 + b)
        run_gemm(s, nf, HID, msg, HID, a1_W + (size_t)l * 512 * HID, HID,
                 a1_b + l * HID, act, HID, NODES, HID, 1);
        // nf += silu(a @ a2 + b)
        run_gemm(s, act, HID, nullptr, 0, a2_W + (size_t)l * HID * HID, HID,
                 a2_b + l * HID, nf, HID, NODES, HID, 2);
    }

    // final LN + readouts
    layernorm_kernel<<<NODES, 256, 0, s>>>(nf, fln_g, fln_b, h);
    graphmean_kernel<<<BGR, 256, 0, s>>>(h, gf);

    run_gemm(s, h, HID, nullptr, 0, type_W, TYPED, type_b, out, TYPED, NODES, TYPED, 0);
    run_gemm(s, gf, HID, nullptr, 0, polar_W, 6, nullptr,
             out + (size_t)NODES * TYPED, 6, BGR, 6, 0);
    run_gemm(s, h, HID, nullptr, 0, frac_W, 3, nullptr,
             out + (size_t)NODES * TYPED + (size_t)BGR * 6, 3, NODES, 3, 0);
}

// round 2
// speedup vs baseline: 1.6305x; 1.6305x over previous
#include <cuda_runtime.h>
#include <math.h>

// ---------------- problem constants ----------------
#define BGR   128
#define NAT   32
#define NODES 4096
#define HID   256
#define TYPED 100
#define EDIM  66
#define NLAY  4
#define NBLK  2048          // edge blocks (2 nodes each)

// ---------------- scratch (device globals) ----------------
__device__ float g_feat[NODES * 384];
__device__ float g_nf  [NODES * HID];
__device__ float g_h   [NODES * HID];
__device__ float g_P   [NODES * 512];         // [:,0:256]=Pi(+bias), [:,256:512]=Pj
__device__ float g_msg [NODES * HID];
__device__ float g_act [NODES * HID];
__device__ float g_gf  [BGR * HID];
__device__ float g_ef  [(size_t)NBLK * EDIM * 64];   // [blk][66][64] transposed tiles

typedef unsigned long long ull;

__device__ __forceinline__ float silu_f(float x) { return x / (1.0f + __expf(-x)); }

// ---- f32x2 packed-FMA helpers (sm_103a FFMA2 path) ----
__device__ __forceinline__ ull pack_dup(float f) {
    ull r; asm("mov.b64 %0, {%1,%1};" : "=l"(r) : "f"(f)); return r;
}
__device__ __forceinline__ void unpack2(ull v, float& lo, float& hi) {
    asm("mov.b64 {%0,%1}, %2;" : "=f"(lo), "=f"(hi) : "l"(v));
}
__device__ __forceinline__ void fma2(ull& acc, ull a, ull b) {
    asm("fma.rn.f32x2 %0, %1, %2, %0;" : "+l"(acc) : "l"(a), "l"(b));
}

// ---- cp.async helpers ----
__device__ __forceinline__ void cp16(void* sdst, const void* gsrc) {
    unsigned s = (unsigned)__cvta_generic_to_shared(sdst);
    asm volatile("cp.async.cg.shared.global [%0], [%1], 16;" :: "r"(s), "l"(gsrc));
}
__device__ __forceinline__ void cp_commit() { asm volatile("cp.async.commit_group;"); }
template<int N> __device__ __forceinline__ void cp_wait() {
    asm volatile("cp.async.wait_group %0;" :: "n"(N));
}

// ---------------- generic fp32 GEMM (FFMA2 inner loop) ----------------
// C[M,N](ldc) = epilogue( A0[:,0:K0]@W[0:K0,:] + A1[:,0:K1]@W[K0:,:] + bias )
// mode 0: C = v ; mode 1: C = silu(v) ; mode 2: C += silu(v)
#define GBM 64
#define GBN 64
#define GBK 16
__global__ void __launch_bounds__(256) gemm_kernel(
    const float* __restrict__ A0, int K0,
    const float* __restrict__ A1, int K1,
    const float* __restrict__ W, int ldw,
    const float* __restrict__ bias,
    float* __restrict__ C, int ldc,
    int M, int N, int mode)
{
    __shared__ float As[GBK][GBM + 2];
    __shared__ float Wsm[GBK][GBN];
    const int tid = threadIdx.x;
    const int tx = tid & 15;          // 16 col groups (4 cols each)
    const int ty = tid >> 4;          // 16 row groups (4 rows each)
    const int row0 = blockIdx.x * GBM;
    const int col0 = blockIdx.y * GBN;
    const int K = K0 + K1;

    ull acc2[2][4];
    #pragma unroll
    for (int i = 0; i < 2; i++)
        #pragma unroll
        for (int j = 0; j < 4; j++) acc2[i][j] = 0ULL;

    for (int kt = 0; kt < K; kt += GBK) {
        {   // load A tile (64 x 16)
            const int m  = tid >> 2;
            const int kb = (tid & 3) * 4;
            const int gr = row0 + m;
            #pragma unroll
            for (int i = 0; i < 4; i++) {
                const int k  = kb + i;
                const int gk = kt + k;
                float v = 0.0f;
                if (gk < K) {
                    if (gk < K0) v = A0[(size_t)gr * K0 + gk];
                    else         v = A1[(size_t)gr * K1 + (gk - K0)];
                }
                As[k][m] = v;
            }
        }
        #pragma unroll
        for (int i = 0; i < 4; i++) {   // load W tile (16 x 64)
            const int idx = tid + 256 * i;
            const int k = idx >> 6;
            const int n = idx & 63;
            const int gk = kt + k;
            const int gn = col0 + n;
            Wsm[k][n] = (gk < K && gn < N) ? W[(size_t)gk * ldw + gn] : 0.0f;
        }
        __syncthreads();
        #pragma unroll
        for (int k = 0; k < GBK; k++) {
            const ull a0 = *(const ull*)&As[k][ty * 4];
            const ull a1 = *(const ull*)&As[k][ty * 4 + 2];
            const float4 w4 = *(const float4*)&Wsm[k][tx * 4];
            ull wd[4];
            wd[0] = pack_dup(w4.x); wd[1] = pack_dup(w4.y);
            wd[2] = pack_dup(w4.z); wd[3] = pack_dup(w4.w);
            #pragma unroll
            for (int j = 0; j < 4; j++) { fma2(acc2[0][j], a0, wd[j]); fma2(acc2[1][j], a1, wd[j]); }
        }
        __syncthreads();
    }

    #pragma unroll
    for (int i2 = 0; i2 < 2; i2++) {
        #pragma unroll
        for (int j = 0; j < 4; j++) {
            float lo, hi; unpack2(acc2[i2][j], lo, hi);
            const int c = col0 + tx * 4 + j;
            if (c >= N) continue;
            const int ra = row0 + ty * 4 + 2 * i2;
            float pair[2] = {lo, hi};
            #pragma unroll
            for (int u = 0; u < 2; u++) {
                const int r = ra + u;
                if (r >= M) continue;
                float v = pair[u];
                if (bias) v += bias[c];
                if (mode == 1)      v = silu_f(v);
                else if (mode == 2) v = C[(size_t)r * ldc + c] + silu_f(v);
                C[(size_t)r * ldc + c] = v;
            }
        }
    }
}

// ---------------- time embedding -> feat[:,256:384] ----------------
__global__ void timefeat_kernel(const float* __restrict__ t, float* __restrict__ feat)
{
    const int idx = blockIdx.x * blockDim.x + threadIdx.x;
    if (idx >= NODES * 128) return;
    const int node = idx >> 7;
    const int c = idx & 127;
    const int b = node >> 5;
    const float tv = t[b];
    const float kfac = -logf(10000.0f) / 63.0f;
    float val;
    if (c < 64) val = sinf(tv * __expf((float)c * kfac));
    else        val = cosf(tv * __expf((float)(c - 64) * kfac));
    feat[(size_t)node * 384 + 256 + c] = val;
}

// ---------------- edge features, transposed per-block tiles ----------------
// layout: eft[bl][k(66)][r(64)], node = 2*bl + (r>>5), j = r&31
__global__ void edgefeat_kernel(const float* __restrict__ frac,
                                const float* __restrict__ lpolar,
                                float* __restrict__ eft)
{
    const int TOT = NBLK * EDIM * 64;
    int idx = blockIdx.x * blockDim.x + threadIdx.x;
    if (idx >= TOT) return;
    const int bl = idx / (EDIM * 64);
    const int rem = idx - bl * (EDIM * 64);
    const int k = rem >> 6;
    const int r = rem & 63;
    const int node = (bl << 1) + (r >> 5);
    const int j = r & 31;
    const int b = node >> 5;

    float val;
    if (k < 60) {
        const int cc  = (k < 30) ? k : (k - 30);
        const int dim = cc / 10;
        const int f   = cc - dim * 10;
        float d = frac[(b * 32 + j) * 3 + dim] - frac[node * 3 + dim];
        d -= floorf(d);
        const float arg = d * (6.283185307179586f * (float)f);
        val = (k < 30) ? sinf(arg) : cosf(arg);
    } else {
        val = lpolar[b * 6 + (k - 60)];
    }
    eft[idx] = val;
}

// ---------------- layernorm ----------------
__global__ void layernorm_kernel(const float* __restrict__ x,
                                 const float* __restrict__ g,
                                 const float* __restrict__ b,
                                 float* __restrict__ y)
{
    const int row = blockIdx.x;
    const int tid = threadIdx.x;
    const float v = x[(size_t)row * HID + tid];
    __shared__ float sred[8];

    float s = v;
    #pragma unroll
    for (int o = 16; o; o >>= 1) s += __shfl_xor_sync(0xffffffffu, s, o);
    if ((tid & 31) == 0) sred[tid >> 5] = s;
    __syncthreads();
    float tot = 0.0f;
    #pragma unroll
    for (int i = 0; i < 8; i++) tot += sred[i];
    const float mean = tot * (1.0f / 256.0f);
    const float d = v - mean;
    __syncthreads();

    float q = d * d;
    #pragma unroll
    for (int o = 16; o; o >>= 1) q += __shfl_xor_sync(0xffffffffu, q, o);
    if ((tid & 31) == 0) sred[tid >> 5] = q;
    __syncthreads();
    tot = 0.0f;
    #pragma unroll
    for (int i = 0; i < 8; i++) tot += sred[i];
    const float var = tot * (1.0f / 256.0f);

    y[(size_t)row * HID + tid] = d * rsqrtf(var + 1e-5f) * g[tid] + b[tid];
}

// ---------------- fused edge-message kernel (2 nodes / block) ----------------
// phase0: E = ef(64x66) @ W1c(66x256); X = silu(E + Pi + Pj)  -> XsT smem
// phase2: Y = X @ W2 (cp.async double-buffered); epilogue silu + mean over 32 j
#define XPAD 68
__global__ void __launch_bounds__(256, 1) edge_msg_kernel(
    const float* __restrict__ P,
    const float* __restrict__ eft,
    const float* __restrict__ W1c,
    const float* __restrict__ W2,
    const float* __restrict__ b2,
    float* __restrict__ msg)
{
    extern __shared__ float smx[];
    float* XsT  = smx;                   // [256][68]
    float* W1s  = XsT + 256 * XPAD;      // [66][256]
    float* W2b0 = W1s + EDIM * 256;      // [32][256]
    float* W2b1 = W2b0 + 32 * 256;       // [32][256]
    float* efs  = W2b1 + 32 * 256;       // [66][64]; aliased with red[8][256]
    float* red  = efs;

    const int bl = blockIdx.x;
    const int node0 = bl << 1;
    const int gb = node0 >> 5;
    const int tid = threadIdx.x;
    const int tx = tid & 31;             // col group: cols {4tx+q, 128+4tx+q}
    const int ty = tid >> 5;             // row group: rows ty*8 .. ty*8+7

    // ---- prefetch: G0 = ef + W1c, G1 = W2 chunk0, G2 = W2 chunk1 ----
    {
        const float4* g = (const float4*)(eft + (size_t)bl * (EDIM * 64));
        for (int i = tid; i < EDIM * 16; i += 256) cp16(((float4*)efs) + i, g + i);
        const float4* gw = (const float4*)W1c;
        for (int i = tid; i < EDIM * 64; i += 256) cp16(((float4*)W1s) + i, gw + i);
    }
    cp_commit();
    {
        const float4* gw = (const float4*)W2;
        #pragma unroll
        for (int q = 0; q < 8; q++) cp16(((float4*)W2b0) + tid + 256 * q, gw + tid + 256 * q);
        cp_commit();
        gw += 2048;
        #pragma unroll
        for (int q = 0; q < 8; q++) cp16(((float4*)W2b1) + tid + 256 * q, gw + tid + 256 * q);
        cp_commit();
    }

    cp_wait<2>();          // ef + W1c ready
    __syncthreads();

    // ---- phase 0: E = ef @ W1c, 8x8 tile/thread, row-paired f32x2 accs ----
    ull acc[4][8];
    #pragma unroll
    for (int p = 0; p < 4; p++)
        #pragma unroll
        for (int c = 0; c < 8; c++) acc[p][c] = 0ULL;

    #pragma unroll 2
    for (int k = 0; k < EDIM; k++) {
        ull ap[4];
        #pragma unroll
        for (int p = 0; p < 4; p++)
            ap[p] = *(const ull*)(efs + k * 64 + ty * 8 + 2 * p);
        const float4 wa = *(const float4*)(W1s + k * 256 + 4 * tx);
        const float4 wb = *(const float4*)(W1s + k * 256 + 128 + 4 * tx);
        ull wd[8];
        wd[0] = pack_dup(wa.x); wd[1] = pack_dup(wa.y); wd[2] = pack_dup(wa.z); wd[3] = pack_dup(wa.w);
        wd[4] = pack_dup(wb.x); wd[5] = pack_dup(wb.y); wd[6] = pack_dup(wb.z); wd[7] = pack_dup(wb.w);
        #pragma unroll
        for (int p = 0; p < 4; p++)
            #pragma unroll
            for (int c = 0; c < 8; c++) fma2(acc[p][c], ap[p], wd[c]);
    }

    // ---- phase 1: X = silu(E + Pi + Pj) -> XsT[col][row] ----
    {
        const int node = node0 + (ty >> 2);
        float pi[8];
        *(float4*)pi       = *(const float4*)(P + (size_t)node * 512 + 4 * tx);
        *(float4*)(pi + 4) = *(const float4*)(P + (size_t)node * 512 + 128 + 4 * tx);
        #pragma unroll
        for (int p = 0; p < 4; p++) {
            const int r0 = ty * 8 + 2 * p;
            const int j0 = r0 & 31;     // even, j0+1 stays in-graph
            const float* pjb0 = P + (size_t)(gb * 32 + j0) * 512 + 256;
            const float* pjb1 = pjb0 + 512;
            float pj0[8], pj1[8];
            *(float4*)pj0       = *(const float4*)(pjb0 + 4 * tx);
            *(float4*)(pj0 + 4) = *(const float4*)(pjb0 + 128 + 4 * tx);
            *(float4*)pj1       = *(const float4*)(pjb1 + 4 * tx);
            *(float4*)(pj1 + 4) = *(const float4*)(pjb1 + 128 + 4 * tx);
            #pragma unroll
            for (int c = 0; c < 8; c++) {
                float e0, e1; unpack2(acc[p][c], e0, e1);
                const int col = ((c >> 2) << 7) + 4 * tx + (c & 3);
                XsT[col * XPAD + r0]     = silu_f(e0 + pi[c] + pj0[c]);
                XsT[col * XPAD + r0 + 1] = silu_f(e1 + pi[c] + pj1[c]);
            }
        }
    }
    __syncthreads();

    // ---- phase 2: Y = X @ W2, 8 chunks of 32 k, double-buffered ----
    ull acc2[4][8];
    #pragma unroll
    for (int p = 0; p < 4; p++)
        #pragma unroll
        for (int c = 0; c < 8; c++) acc2[p][c] = 0ULL;

    #pragma unroll 1
    for (int ch = 0; ch < 8; ch++) {
        cp_wait<1>();
        __syncthreads();
        const float* Wb = (ch & 1) ? W2b1 : W2b0;
        const int kbase = ch * 32;
        #pragma unroll 2
        for (int kl = 0; kl < 32; kl++) {
            const int k = kbase + kl;
            ull ap[4];
            #pragma unroll
            for (int p = 0; p < 4; p++)
                ap[p] = *(const ull*)(XsT + k * XPAD + ty * 8 + 2 * p);
            const float4 wa = *(const float4*)(Wb + kl * 256 + 4 * tx);
            const float4 wb4 = *(const float4*)(Wb + kl * 256 + 128 + 4 * tx);
            ull wd[8];
            wd[0] = pack_dup(wa.x);  wd[1] = pack_dup(wa.y);  wd[2] = pack_dup(wa.z);  wd[3] = pack_dup(wa.w);
            wd[4] = pack_dup(wb4.x); wd[5] = pack_dup(wb4.y); wd[6] = pack_dup(wb4.z); wd[7] = pack_dup(wb4.w);
            #pragma unroll
            for (int p = 0; p < 4; p++)
                #pragma unroll
                for (int c = 0; c < 8; c++) fma2(acc2[p][c], ap[p], wd[c]);
        }
        __syncthreads();
        if (ch < 6) {
            const float4* gw = (const float4*)W2 + (size_t)(ch + 2) * 2048;
            float* dst = (ch & 1) ? W2b1 : W2b0;
            #pragma unroll
            for (int q = 0; q < 8; q++) cp16(((float4*)dst) + tid + 256 * q, gw + tid + 256 * q);
        }
        cp_commit();   // always commit to keep group accounting uniform
    }

    // ---- epilogue: bias + silu + mean over j, per node ----
    {
        float bb[8];
        *(float4*)bb       = *(const float4*)(b2 + 4 * tx);
        *(float4*)(bb + 4) = *(const float4*)(b2 + 128 + 4 * tx);
        float s[8];
        #pragma unroll
        for (int c = 0; c < 8; c++) s[c] = 0.0f;
        #pragma unroll
        for (int p = 0; p < 4; p++)
            #pragma unroll
            for (int c = 0; c < 8; c++) {
                float v0, v1; unpack2(acc2[p][c], v0, v1);
                s[c] += silu_f(v0 + bb[c]) + silu_f(v1 + bb[c]);
            }
        #pragma unroll
        for (int c = 0; c < 8; c++) {
            const int col = ((c >> 2) << 7) + 4 * tx + (c & 3);
            red[ty * 256 + col] = s[c];
        }
    }
    __syncthreads();
    {
        const int c = tid;
        const float m0 = red[c] + red[256 + c] + red[512 + c] + red[768 + c];
        const float m1 = red[1024 + c] + red[1280 + c] + red[1536 + c] + red[1792 + c];
        msg[(size_t)node0 * 256 + c]       = m0 * 0.03125f;
        msg[(size_t)(node0 + 1) * 256 + c] = m1 * 0.03125f;
    }
}

// ---------------- graph mean ----------------
__global__ void graphmean_kernel(const float* __restrict__ h, float* __restrict__ gf)
{
    const int b = blockIdx.x;
    const int c = threadIdx.x;
    float s = 0.0f;
    #pragma unroll
    for (int i = 0; i < 32; i++) s += h[(size_t)((b << 5) + i) * HID + c];
    gf[(size_t)b * HID + c] = s * (1.0f / 32.0f);
}

// ---------------- host launch ----------------
static void run_gemm(cudaStream_t s,
                     const float* A0, int K0, const float* A1, int K1,
                     const float* W, int ldw, const float* bias,
                     float* C, int ldc, int M, int N, int mode)
{
    dim3 grid((M + GBM - 1) / GBM, (N + GBN - 1) / GBN);
    gemm_kernel<<<grid, 256, 0, s>>>(A0, K0, A1, K1, W, ldw, bias, C, ldc, M, N, mode);
}

extern "C" void kernel_launch(void* const* d_in, const int* in_sizes, int n_in,
                              void* d_out, int out_size)
{
    const float* t          = (const float*)d_in[0];
    const float* atom_types = (const float*)d_in[1];
    const float* frac       = (const float*)d_in[2];
    const float* l_polar    = (const float*)d_in[3];
    const float* Ws      = (const float*)d_in[5];
    const float* bs      = (const float*)d_in[6];
    const float* Wn      = (const float*)d_in[7];
    const float* bn      = (const float*)d_in[8];
    const float* ln_g    = (const float*)d_in[9];
    const float* ln_b    = (const float*)d_in[10];
    const float* m1_W    = (const float*)d_in[11];
    const float* m1_b    = (const float*)d_in[12];
    const float* m2_W    = (const float*)d_in[13];
    const float* m2_b    = (const float*)d_in[14];
    const float* a1_W    = (const float*)d_in[15];
    const float* a1_b    = (const float*)d_in[16];
    const float* a2_W    = (const float*)d_in[17];
    const float* a2_b    = (const float*)d_in[18];
    const float* fln_g   = (const float*)d_in[19];
    const float* fln_b   = (const float*)d_in[20];
    const float* type_W  = (const float*)d_in[21];
    const float* type_b  = (const float*)d_in[22];
    const float* polar_W = (const float*)d_in[23];
    const float* frac_W  = (const float*)d_in[24];
    float* out = (float*)d_out;

    float *feat, *nf, *h, *P, *msg, *act, *gf, *ef;
    cudaGetSymbolAddress((void**)&feat, g_feat);
    cudaGetSymbolAddress((void**)&nf,   g_nf);
    cudaGetSymbolAddress((void**)&h,    g_h);
    cudaGetSymbolAddress((void**)&P,    g_P);
    cudaGetSymbolAddress((void**)&msg,  g_msg);
    cudaGetSymbolAddress((void**)&act,  g_act);
    cudaGetSymbolAddress((void**)&gf,   g_gf);
    cudaGetSymbolAddress((void**)&ef,   g_ef);

    const int EDGE_SMEM = (256 * XPAD + EDIM * 256 + 64 * 256 + EDIM * 64) * (int)sizeof(float);
    cudaFuncSetAttribute(edge_msg_kernel, cudaFuncAttributeMaxDynamicSharedMemorySize, EDGE_SMEM);

    cudaStream_t s = 0;

    // node features
    timefeat_kernel<<<(NODES * 128 + 255) / 256, 256, 0, s>>>(t, feat);
    run_gemm(s, atom_types, TYPED, nullptr, 0, Ws, HID, bs, feat, 384, NODES, HID, 0);
    run_gemm(s, feat, 384, nullptr, 0, Wn, HID, bn, nf, HID, NODES, HID, 0);

    // edge features (layer-independent), transposed tiles
    {
        const int TOT = NBLK * EDIM * 64;
        edgefeat_kernel<<<(TOT + 255) / 256, 256, 0, s>>>(frac, l_polar, ef);
    }

    for (int l = 0; l < NLAY; l++) {
        const float* W1 = m1_W + (size_t)l * 578 * HID;
        layernorm_kernel<<<NODES, 256, 0, s>>>(nf, ln_g + l * HID, ln_b + l * HID, h);
        // P[:,0:256] = h @ W1[0:256] + m1_b ; P[:,256:512] = h @ W1[256:512]
        run_gemm(s, h, HID, nullptr, 0, W1, HID, m1_b + l * HID, P, 512, NODES, HID, 0);
        run_gemm(s, h, HID, nullptr, 0, W1 + 256 * HID, HID, nullptr, P + 256, 512, NODES, HID, 0);
        // fused edge path
        edge_msg_kernel<<<NBLK, 256, EDGE_SMEM, s>>>(
            P, ef, W1 + 512 * HID, m2_W + (size_t)l * HID * HID, m2_b + l * HID, msg);
        // a = silu(concat(nf,msg) @ a1 + b)
        run_gemm(s, nf, HID, msg, HID, a1_W + (size_t)l * 512 * HID, HID,
                 a1_b + l * HID, act, HID, NODES, HID, 1);
        // nf += silu(a @ a2 + b)
        run_gemm(s, act, HID, nullptr, 0, a2_W + (size_t)l * HID * HID, HID,
                 a2_b + l * HID, nf, HID, NODES, HID, 2);
    }

    layernorm_kernel<<<NODES, 256, 0, s>>>(nf, fln_g, fln_b, h);
    graphmean_kernel<<<BGR, 256, 0, s>>>(h, gf);

    run_gemm(s, h, HID, nullptr, 0, type_W, TYPED, type_b, out, TYPED, NODES, TYPED, 0);
    run_gemm(s, gf, HID, nullptr, 0, polar_W, 6, nullptr,
             out + (size_t)NODES * TYPED, 6, BGR, 6, 0);
    run_gemm(s, h, HID, nullptr, 0, frac_W, 3, nullptr,
             out + (size_t)NODES * TYPED + (size_t)BGR * 6, 3, NODES, 3, 0);
}